// round 6
// baseline (speedup 1.0000x reference)
#include <cuda_runtime.h>
#include <cuda_bf16.h>
#include <cstdint>
#include <cstddef>

// ============================================================================
// Problem dims
// ============================================================================
#define MM 8192
#define KK 4096
#define NN 4096

// ============================================================================
// Device scratch (allowed: __device__ globals, no runtime allocation)
// ============================================================================
__device__ unsigned g_amax_x;
__device__ unsigned g_amax_w;
__device__ __nv_bfloat16 g_xq[(size_t)MM * KK];   // quantized activations (exact ints in bf16)
__device__ __nv_bfloat16 g_wq[(size_t)NN * KK];   // quantized weights

// ============================================================================
// PTX helpers — family-generic (sm_80+ PTX only; NO tcgen05 on this target!)
// ============================================================================
__device__ __forceinline__ uint32_t smem_u32(const void* p) {
    uint32_t a;
    asm("{ .reg .u64 t; cvta.to.shared.u64 t, %1; cvt.u32.u64 %0, t; }" : "=r"(a) : "l"(p));
    return a;
}

#define CP_ASYNC16(dst, src) \
    asm volatile("cp.async.cg.shared.global [%0], [%1], 16;" :: "r"(dst), "l"(src) : "memory")
#define CP_COMMIT() asm volatile("cp.async.commit_group;" ::: "memory")
#define CP_WAIT2()  asm volatile("cp.async.wait_group 2;" ::: "memory")
#define CP_WAIT0()  asm volatile("cp.async.wait_group 0;" ::: "memory")

// bf16 warp MMA: D(16x8,f32) = A(16x16,bf16,row) * B(16x8,bf16,col) + D
__device__ __forceinline__ void hmma16816(float* c, const uint32_t* a, const uint32_t* b) {
    asm volatile(
        "mma.sync.aligned.m16n8k16.row.col.f32.bf16.bf16.f32 "
        "{%0,%1,%2,%3}, {%4,%5,%6,%7}, {%8,%9}, {%0,%1,%2,%3};"
        : "+f"(c[0]), "+f"(c[1]), "+f"(c[2]), "+f"(c[3])
        : "r"(a[0]), "r"(a[1]), "r"(a[2]), "r"(a[3]), "r"(b[0]), "r"(b[1]));
}

// ldmatrix x4: four 8x8 b16 matrices; lane l supplies the row address for its group
__device__ __forceinline__ void ldsm_x4(uint32_t* r, uint32_t addr) {
    asm volatile("ldmatrix.sync.aligned.m8n8.x4.shared.b16 {%0,%1,%2,%3}, [%4];"
                 : "=r"(r[0]), "=r"(r[1]), "=r"(r[2]), "=r"(r[3]) : "r"(addr));
}

// ============================================================================
// Pass 1: reset + abs-max reductions
// ============================================================================
__global__ void reset_kernel() {
    g_amax_x = 0u;
    g_amax_w = 0u;
}

__global__ void absmax_kernel(const float* __restrict__ in, long n4, int which) {
    float m = 0.0f;
    long i = (long)blockIdx.x * blockDim.x + threadIdx.x;
    long stride = (long)gridDim.x * blockDim.x;
    const float4* in4 = reinterpret_cast<const float4*>(in);
    for (; i < n4; i += stride) {
        float4 v = in4[i];
        m = fmaxf(m, fmaxf(fmaxf(fabsf(v.x), fabsf(v.y)), fmaxf(fabsf(v.z), fabsf(v.w))));
    }
    #pragma unroll
    for (int o = 16; o > 0; o >>= 1)
        m = fmaxf(m, __shfl_xor_sync(0xFFFFFFFFu, m, o));
    if ((threadIdx.x & 31) == 0)
        atomicMax(which ? &g_amax_w : &g_amax_x, __float_as_uint(m));
}

// ============================================================================
// Pass 2: quantize — exact match to jnp: clip(rint(t/scale), ±127)
// Values are integers in [-127,127]: exactly representable in bf16.
// ============================================================================
__global__ void quant_kernel(const float* __restrict__ in, long n4, int which) {
    float amax = __uint_as_float(which ? g_amax_w : g_amax_x);
    float scale = amax / 127.0f;
    __nv_bfloat16* q = which ? g_wq : g_xq;
    long i = (long)blockIdx.x * blockDim.x + threadIdx.x;
    long stride = (long)gridDim.x * blockDim.x;
    const float4* in4 = reinterpret_cast<const float4*>(in);
    __nv_bfloat162* q2 = reinterpret_cast<__nv_bfloat162*>(q);
    for (; i < n4; i += stride) {
        float4 v = in4[i];
        float a = fminf(fmaxf(rintf(v.x / scale), -127.0f), 127.0f);
        float b = fminf(fmaxf(rintf(v.y / scale), -127.0f), 127.0f);
        float c = fminf(fmaxf(rintf(v.z / scale), -127.0f), 127.0f);
        float d = fminf(fmaxf(rintf(v.w / scale), -127.0f), 127.0f);
        q2[2 * i + 0] = __floats2bfloat162_rn(a, b);
        q2[2 * i + 1] = __floats2bfloat162_rn(c, d);
    }
}

// ============================================================================
// Pass 3: bf16 GEMM  out[M,N] = Xq[M,K] @ Wq[N,K]^T * s + bias
//   BM=256, BN=256, BK=32 (64B rows, 80B padded); 512 threads = 16 warps (4x4
//   grid of 64x64 warp tiles); ldmatrix.x4 fragment loads; 4-stage cp.async.
// ============================================================================
static constexpr int BK = 32;                  // bf16 elems per K chunk (64B rows)
static constexpr int NKT = KK / BK;            // 128 k-tiles
static constexpr int ROW_PAD = 80;             // 64B data + 16B pad (conflict-free)
static constexpr int A_STAGE = 256 * ROW_PAD;  // 20480 B
static constexpr int STAGE_BYTES = 2 * A_STAGE;// A + B = 40960 B
static constexpr int NSTAGE = 4;
static constexpr int SMEM_BYTES = NSTAGE * STAGE_BYTES;  // 163840 B

__device__ __forceinline__ void stage_copy(uint32_t sbase, int kt, int m0, int n0, int tid) {
    const size_t kofs = (size_t)kt * BK;       // element offset
    #pragma unroll
    for (int i = 0; i < 2; i++) {
        int idx = tid + i * 512;               // 0..1023
        int row = idx >> 2, ch = idx & 3;      // 4 x 16B chunks per 64B row
        CP_ASYNC16(sbase + row * ROW_PAD + ch * 16,
                   (const void*)(g_xq + (size_t)(m0 + row) * KK + kofs + ch * 8));
    }
    #pragma unroll
    for (int i = 0; i < 2; i++) {
        int idx = tid + i * 512;
        int row = idx >> 2, ch = idx & 3;
        CP_ASYNC16(sbase + A_STAGE + row * ROW_PAD + ch * 16,
                   (const void*)(g_wq + (size_t)(n0 + row) * KK + kofs + ch * 8));
    }
}

extern "C" __global__ void __launch_bounds__(512, 1)
gemm_kernel(const float* __restrict__ bias, float* __restrict__ out) {
    extern __shared__ char smem[];
    const uint32_t sb = smem_u32(smem);
    const int tid = threadIdx.x;
    const int wid = tid >> 5;
    const int lane = tid & 31;
    const int warp_m = wid & 3;          // 4 warps along M
    const int warp_n = wid >> 2;         // 4 warps along N
    const int m0 = blockIdx.y * 256;
    const int n0 = blockIdx.x * 256;

    float c[4][8][4];
    #pragma unroll
    for (int mt = 0; mt < 4; mt++)
        #pragma unroll
        for (int nt = 0; nt < 8; nt++)
            #pragma unroll
            for (int j = 0; j < 4; j++) c[mt][nt][j] = 0.0f;

    // Prologue: fill stages 0..2
    #pragma unroll
    for (int s = 0; s < NSTAGE - 1; s++) {
        stage_copy(sb + s * STAGE_BYTES, s, m0, n0, tid);
        CP_COMMIT();
    }

    // ldmatrix lane addressing: row = lane&15, +16B for lanes 16..31
    const int lrow = lane & 15;
    const int lhalf = (lane >> 4) * 16;

    for (int kt = 0; kt < NKT; kt++) {
        CP_WAIT2();
        __syncthreads();

        if (kt + NSTAGE - 1 < NKT)
            stage_copy(sb + ((kt + NSTAGE - 1) & (NSTAGE - 1)) * STAGE_BYTES,
                       kt + NSTAGE - 1, m0, n0, tid);
        CP_COMMIT();

        const uint32_t sA = sb + (kt & (NSTAGE - 1)) * STAGE_BYTES;
        const uint32_t sB = sA + A_STAGE;

        // Two k16 sub-steps within the 32-elem (64B) K chunk
        #pragma unroll
        for (int kp = 0; kp < 2; kp++) {
            // A frags: r0=(m0-7,k0-7) r1=(m8-15,k0-7) r2=(m0-7,k8-15) r3=(m8-15,k8-15)
            uint32_t a[4][4];
            #pragma unroll
            for (int mt = 0; mt < 4; mt++)
                ldsm_x4(a[mt], sA + (warp_m * 64 + mt * 16 + lrow) * ROW_PAD + kp * 32 + lhalf);
            // B frags: pair of nt per ldmatrix: r0=b0(even) r1=b0(odd) r2=b1(even) r3=b1(odd)
            uint32_t b[8][2];
            #pragma unroll
            for (int np = 0; np < 4; np++) {
                uint32_t r[4];
                ldsm_x4(r, sB + (warp_n * 64 + np * 16 + lrow) * ROW_PAD + kp * 32 + lhalf);
                b[2 * np + 0][0] = r[0]; b[2 * np + 0][1] = r[2];
                b[2 * np + 1][0] = r[1]; b[2 * np + 1][1] = r[3];
            }
            #pragma unroll
            for (int mt = 0; mt < 4; mt++)
                #pragma unroll
                for (int nt = 0; nt < 8; nt++)
                    hmma16816(c[mt][nt], a[mt], b[nt]);
        }
        __syncthreads();
    }
    CP_WAIT0();

    // Epilogue: dequant + bias
    const float sx = __uint_as_float(g_amax_x) / 127.0f;
    const float sw = __uint_as_float(g_amax_w) / 127.0f;
    const float s = sx * sw;

    #pragma unroll
    for (int mt = 0; mt < 4; mt++) {
        #pragma unroll
        for (int half = 0; half < 2; half++) {
            int row = m0 + warp_m * 64 + mt * 16 + (lane >> 2) + half * 8;
            float* orow = out + (size_t)row * NN;
            #pragma unroll
            for (int nt = 0; nt < 8; nt++) {
                int col = n0 + warp_n * 64 + nt * 8 + (lane & 3) * 2;
                float2 o;
                o.x = c[mt][nt][half * 2 + 0] * s + __ldg(&bias[col]);
                o.y = c[mt][nt][half * 2 + 1] * s + __ldg(&bias[col + 1]);
                *reinterpret_cast<float2*>(orow + col) = o;
            }
        }
    }
}

// ============================================================================
// kernel_launch — graph-capturable, allocation-free
// ============================================================================
extern "C" void kernel_launch(void* const* d_in, const int* in_sizes, int n_in,
                              void* d_out, int out_size) {
    const float* x    = (const float*)d_in[0];   // [M, K]
    const float* w    = (const float*)d_in[1];   // [N, K]
    const float* bias = (const float*)d_in[2];   // [N]
    float* out        = (float*)d_out;           // [M, N]

    reset_kernel<<<1, 1>>>();
    absmax_kernel<<<2048, 256>>>(x, (long)MM * KK / 4, 0);
    absmax_kernel<<<1024, 256>>>(w, (long)NN * KK / 4, 1);
    quant_kernel<<<8192, 256>>>(x, (long)MM * KK / 4, 0);
    quant_kernel<<<4096, 256>>>(w, (long)NN * KK / 4, 1);

    static bool attr_set = false;
    if (!attr_set) {
        cudaFuncSetAttribute(gemm_kernel, cudaFuncAttributeMaxDynamicSharedMemorySize, SMEM_BYTES);
        attr_set = true;
    }
    gemm_kernel<<<dim3(NN / 256, MM / 256, 1), 512, SMEM_BYTES>>>(bias, out);
}

// round 7
// speedup vs baseline: 2.2340x; 2.2340x over previous
#include <cuda_runtime.h>
#include <cuda_bf16.h>
#include <cstdint>
#include <cstddef>

// ============================================================================
// Problem dims
// ============================================================================
#define MM 8192
#define KK 4096
#define NN 4096

// ============================================================================
// Device scratch (allowed: __device__ globals, no runtime allocation)
// ============================================================================
__device__ unsigned g_amax_x;
__device__ unsigned g_amax_w;
__device__ __nv_bfloat16 g_xq[(size_t)MM * KK];   // quantized activations (exact ints in bf16)
__device__ __nv_bfloat16 g_wq[(size_t)NN * KK];   // quantized weights

// ============================================================================
// PTX helpers — family-generic (sm_80+ PTX only; NO tcgen05 on this target!)
// ============================================================================
__device__ __forceinline__ uint32_t smem_u32(const void* p) {
    uint32_t a;
    asm("{ .reg .u64 t; cvta.to.shared.u64 t, %1; cvt.u32.u64 %0, t; }" : "=r"(a) : "l"(p));
    return a;
}

#define CP_ASYNC16(dst, src) \
    asm volatile("cp.async.cg.shared.global [%0], [%1], 16;" :: "r"(dst), "l"(src) : "memory")
#define CP_COMMIT() asm volatile("cp.async.commit_group;" ::: "memory")
#define CP_WAIT2()  asm volatile("cp.async.wait_group 2;" ::: "memory")
#define CP_WAIT0()  asm volatile("cp.async.wait_group 0;" ::: "memory")

// bf16 warp MMA: D(16x8,f32) = A(16x16,bf16,row) * B(16x8,bf16,col) + D
__device__ __forceinline__ void hmma16816(float* c, const uint32_t* a, const uint32_t* b) {
    asm volatile(
        "mma.sync.aligned.m16n8k16.row.col.f32.bf16.bf16.f32 "
        "{%0,%1,%2,%3}, {%4,%5,%6,%7}, {%8,%9}, {%0,%1,%2,%3};"
        : "+f"(c[0]), "+f"(c[1]), "+f"(c[2]), "+f"(c[3])
        : "r"(a[0]), "r"(a[1]), "r"(a[2]), "r"(a[3]), "r"(b[0]), "r"(b[1]));
}

// ldmatrix x4: four 8x8 b16 matrices; lane l supplies the row address for its group
__device__ __forceinline__ void ldsm_x4(uint32_t* r, uint32_t addr) {
    asm volatile("ldmatrix.sync.aligned.m8n8.x4.shared.b16 {%0,%1,%2,%3}, [%4];"
                 : "=r"(r[0]), "=r"(r[1]), "=r"(r[2]), "=r"(r[3]) : "r"(addr));
}

// ============================================================================
// Pass 1: reset + abs-max reductions
// ============================================================================
__global__ void reset_kernel() {
    g_amax_x = 0u;
    g_amax_w = 0u;
}

__global__ void absmax_kernel(const float* __restrict__ in, long n4, int which) {
    float m = 0.0f;
    long i = (long)blockIdx.x * blockDim.x + threadIdx.x;
    long stride = (long)gridDim.x * blockDim.x;
    const float4* in4 = reinterpret_cast<const float4*>(in);
    for (; i < n4; i += stride) {
        float4 v = in4[i];
        m = fmaxf(m, fmaxf(fmaxf(fabsf(v.x), fabsf(v.y)), fmaxf(fabsf(v.z), fabsf(v.w))));
    }
    #pragma unroll
    for (int o = 16; o > 0; o >>= 1)
        m = fmaxf(m, __shfl_xor_sync(0xFFFFFFFFu, m, o));
    if ((threadIdx.x & 31) == 0)
        atomicMax(which ? &g_amax_w : &g_amax_x, __float_as_uint(m));
}

// ============================================================================
// Pass 2: quantize — exact match to jnp: clip(rint(t/scale), ±127)
// Values are integers in [-127,127]: exactly representable in bf16.
// ============================================================================
__global__ void quant_kernel(const float* __restrict__ in, long n4, int which) {
    float amax = __uint_as_float(which ? g_amax_w : g_amax_x);
    float scale = amax / 127.0f;
    __nv_bfloat16* q = which ? g_wq : g_xq;
    long i = (long)blockIdx.x * blockDim.x + threadIdx.x;
    long stride = (long)gridDim.x * blockDim.x;
    const float4* in4 = reinterpret_cast<const float4*>(in);
    __nv_bfloat162* q2 = reinterpret_cast<__nv_bfloat162*>(q);
    for (; i < n4; i += stride) {
        float4 v = in4[i];
        float a = fminf(fmaxf(rintf(v.x / scale), -127.0f), 127.0f);
        float b = fminf(fmaxf(rintf(v.y / scale), -127.0f), 127.0f);
        float c = fminf(fmaxf(rintf(v.z / scale), -127.0f), 127.0f);
        float d = fminf(fmaxf(rintf(v.w / scale), -127.0f), 127.0f);
        q2[2 * i + 0] = __floats2bfloat162_rn(a, b);
        q2[2 * i + 1] = __floats2bfloat162_rn(c, d);
    }
}

// ============================================================================
// Pass 3: bf16 GEMM  out[M,N] = Xq[M,K] @ Wq[N,K]^T * s + bias
//   BM=256, BN=128, BK=32; 256 threads = 8 warps (4x2 grid of 64x64 tiles)
//   ldmatrix.x4 fragment loads; 4-stage cp.async; 80B-padded rows.
//   256 threads -> 256-reg budget/thread: no spills (the round-6 bug).
// ============================================================================
static constexpr int BK = 32;                  // bf16 elems per K chunk (64B rows)
static constexpr int NKT = KK / BK;            // 128 k-tiles
static constexpr int ROW_PAD = 80;             // 64B data + 16B pad (conflict-free)
static constexpr int A_STAGE = 256 * ROW_PAD;  // 20480 B
static constexpr int B_STAGE = 128 * ROW_PAD;  // 10240 B
static constexpr int STAGE_BYTES = A_STAGE + B_STAGE;  // 30720 B
static constexpr int NSTAGE = 4;
static constexpr int SMEM_BYTES = NSTAGE * STAGE_BYTES;  // 122880 B

__device__ __forceinline__ void stage_copy(uint32_t sbase, int kt, int m0, int n0, int tid) {
    const size_t kofs = (size_t)kt * BK;       // element offset
    // A: 256 rows x 4 chunks = 1024 copies; 4 per thread
    #pragma unroll
    for (int i = 0; i < 4; i++) {
        int idx = tid + i * 256;               // 0..1023
        int row = idx >> 2, ch = idx & 3;      // 4 x 16B chunks per 64B row
        CP_ASYNC16(sbase + row * ROW_PAD + ch * 16,
                   (const void*)(g_xq + (size_t)(m0 + row) * KK + kofs + ch * 8));
    }
    // B: 128 rows x 4 chunks = 512 copies; 2 per thread
    #pragma unroll
    for (int i = 0; i < 2; i++) {
        int idx = tid + i * 256;               // 0..511
        int row = idx >> 2, ch = idx & 3;
        CP_ASYNC16(sbase + A_STAGE + row * ROW_PAD + ch * 16,
                   (const void*)(g_wq + (size_t)(n0 + row) * KK + kofs + ch * 8));
    }
}

extern "C" __global__ void __launch_bounds__(256, 1)
gemm_kernel(const float* __restrict__ bias, float* __restrict__ out) {
    extern __shared__ char smem[];
    const uint32_t sb = smem_u32(smem);
    const int tid = threadIdx.x;
    const int wid = tid >> 5;
    const int lane = tid & 31;
    const int warp_m = wid & 3;          // 4 warps along M (0..3)
    const int warp_n = wid >> 2;         // 2 warps along N (0..1)
    const int m0 = blockIdx.y * 256;
    const int n0 = blockIdx.x * 128;

    float c[4][8][4];
    #pragma unroll
    for (int mt = 0; mt < 4; mt++)
        #pragma unroll
        for (int nt = 0; nt < 8; nt++)
            #pragma unroll
            for (int j = 0; j < 4; j++) c[mt][nt][j] = 0.0f;

    // Prologue: fill stages 0..2
    #pragma unroll
    for (int s = 0; s < NSTAGE - 1; s++) {
        stage_copy(sb + s * STAGE_BYTES, s, m0, n0, tid);
        CP_COMMIT();
    }

    // ldmatrix lane addressing: row = lane&15, +16B for lanes 16..31
    const int lrow = lane & 15;
    const int lhalf = (lane >> 4) * 16;

    for (int kt = 0; kt < NKT; kt++) {
        CP_WAIT2();
        __syncthreads();

        if (kt + NSTAGE - 1 < NKT)
            stage_copy(sb + ((kt + NSTAGE - 1) & (NSTAGE - 1)) * STAGE_BYTES,
                       kt + NSTAGE - 1, m0, n0, tid);
        CP_COMMIT();

        const uint32_t sA = sb + (kt & (NSTAGE - 1)) * STAGE_BYTES;
        const uint32_t sB = sA + A_STAGE;

        // Two k16 sub-steps within the 32-elem (64B) K chunk
        #pragma unroll
        for (int kp = 0; kp < 2; kp++) {
            // A frags: r0=(m0-7,k0-7) r1=(m8-15,k0-7) r2=(m0-7,k8-15) r3=(m8-15,k8-15)
            uint32_t a[4][4];
            #pragma unroll
            for (int mt = 0; mt < 4; mt++)
                ldsm_x4(a[mt], sA + (warp_m * 64 + mt * 16 + lrow) * ROW_PAD + kp * 32 + lhalf);
            // B frags: pair of nt per ldmatrix: r0=b0(even) r1=b0(odd) r2=b1(even) r3=b1(odd)
            uint32_t b[8][2];
            #pragma unroll
            for (int np = 0; np < 4; np++) {
                uint32_t r[4];
                ldsm_x4(r, sB + (warp_n * 64 + np * 16 + lrow) * ROW_PAD + kp * 32 + lhalf);
                b[2 * np + 0][0] = r[0]; b[2 * np + 0][1] = r[2];
                b[2 * np + 1][0] = r[1]; b[2 * np + 1][1] = r[3];
            }
            #pragma unroll
            for (int mt = 0; mt < 4; mt++)
                #pragma unroll
                for (int nt = 0; nt < 8; nt++)
                    hmma16816(c[mt][nt], a[mt], b[nt]);
        }
        __syncthreads();
    }
    CP_WAIT0();

    // Epilogue: dequant + bias
    const float sx = __uint_as_float(g_amax_x) / 127.0f;
    const float sw = __uint_as_float(g_amax_w) / 127.0f;
    const float s = sx * sw;

    #pragma unroll
    for (int mt = 0; mt < 4; mt++) {
        #pragma unroll
        for (int half = 0; half < 2; half++) {
            int row = m0 + warp_m * 64 + mt * 16 + (lane >> 2) + half * 8;
            float* orow = out + (size_t)row * NN;
            #pragma unroll
            for (int nt = 0; nt < 8; nt++) {
                int col = n0 + warp_n * 64 + nt * 8 + (lane & 3) * 2;
                float2 o;
                o.x = c[mt][nt][half * 2 + 0] * s + __ldg(&bias[col]);
                o.y = c[mt][nt][half * 2 + 1] * s + __ldg(&bias[col + 1]);
                *reinterpret_cast<float2*>(orow + col) = o;
            }
        }
    }
}

// ============================================================================
// kernel_launch — graph-capturable, allocation-free
// ============================================================================
extern "C" void kernel_launch(void* const* d_in, const int* in_sizes, int n_in,
                              void* d_out, int out_size) {
    const float* x    = (const float*)d_in[0];   // [M, K]
    const float* w    = (const float*)d_in[1];   // [N, K]
    const float* bias = (const float*)d_in[2];   // [N]
    float* out        = (float*)d_out;           // [M, N]

    reset_kernel<<<1, 1>>>();
    absmax_kernel<<<2048, 256>>>(x, (long)MM * KK / 4, 0);
    absmax_kernel<<<1024, 256>>>(w, (long)NN * KK / 4, 1);
    quant_kernel<<<8192, 256>>>(x, (long)MM * KK / 4, 0);
    quant_kernel<<<4096, 256>>>(w, (long)NN * KK / 4, 1);

    static bool attr_set = false;
    if (!attr_set) {
        cudaFuncSetAttribute(gemm_kernel, cudaFuncAttributeMaxDynamicSharedMemorySize, SMEM_BYTES);
        attr_set = true;
    }
    gemm_kernel<<<dim3(NN / 128, MM / 256, 1), 256, SMEM_BYTES>>>(bias, out);
}

// round 8
// speedup vs baseline: 2.4482x; 1.0959x over previous
#include <cuda_runtime.h>
#include <cuda_bf16.h>
#include <cstdint>
#include <cstddef>

// ============================================================================
// Problem dims
// ============================================================================
#define MM 8192
#define KK 4096
#define NN 4096

// ============================================================================
// Device scratch (allowed: __device__ globals, no runtime allocation)
// ============================================================================
__device__ unsigned g_amax_x;
__device__ unsigned g_amax_w;
__device__ __nv_bfloat16 g_xq[(size_t)MM * KK];   // quantized activations (exact ints in bf16)
__device__ __nv_bfloat16 g_wq[(size_t)NN * KK];   // quantized weights

// ============================================================================
// PTX helpers — family-generic (sm_80+ PTX only; NO tcgen05 on this target!)
// ============================================================================
__device__ __forceinline__ uint32_t smem_u32(const void* p) {
    uint32_t a;
    asm("{ .reg .u64 t; cvta.to.shared.u64 t, %1; cvt.u32.u64 %0, t; }" : "=r"(a) : "l"(p));
    return a;
}

#define CP_ASYNC16(dst, src) \
    asm volatile("cp.async.cg.shared.global [%0], [%1], 16;" :: "r"(dst), "l"(src) : "memory")
#define CP_COMMIT() asm volatile("cp.async.commit_group;" ::: "memory")
#define CP_WAIT2()  asm volatile("cp.async.wait_group 2;" ::: "memory")
#define CP_WAIT0()  asm volatile("cp.async.wait_group 0;" ::: "memory")

// bf16 warp MMA: D(16x8,f32) = A(16x16,bf16,row) * B(16x8,bf16,col) + D
__device__ __forceinline__ void hmma16816(float* c, const uint32_t* a, const uint32_t* b) {
    asm volatile(
        "mma.sync.aligned.m16n8k16.row.col.f32.bf16.bf16.f32 "
        "{%0,%1,%2,%3}, {%4,%5,%6,%7}, {%8,%9}, {%0,%1,%2,%3};"
        : "+f"(c[0]), "+f"(c[1]), "+f"(c[2]), "+f"(c[3])
        : "r"(a[0]), "r"(a[1]), "r"(a[2]), "r"(a[3]), "r"(b[0]), "r"(b[1]));
}

// ldmatrix x4: four 8x8 b16 matrices; lane l supplies the row address for its group
__device__ __forceinline__ void ldsm_x4(uint32_t* r, uint32_t addr) {
    asm volatile("ldmatrix.sync.aligned.m8n8.x4.shared.b16 {%0,%1,%2,%3}, [%4];"
                 : "=r"(r[0]), "=r"(r[1]), "=r"(r[2]), "=r"(r[3]) : "r"(addr));
}

// ============================================================================
// Pass 0: reset scales (cheap; guarantees determinism for any input)
// ============================================================================
__global__ void reset_kernel() {
    g_amax_x = 0u;
    g_amax_w = 0u;
}

// ============================================================================
// Pass 1: fused abs-max over BOTH tensors in one launch
//   blocks [0, 2048)   -> x   (8192*4096/4 = 8M float4)
//   blocks [2048, 3072) -> w  (4M float4)
// ============================================================================
__global__ void absmax_both_kernel(const float* __restrict__ x, const float* __restrict__ w) {
    const bool is_w = blockIdx.x >= 2048;
    const float4* in4 = reinterpret_cast<const float4*>(is_w ? w : x);
    const long n4 = is_w ? ((long)NN * KK / 4) : ((long)MM * KK / 4);
    const long nb = is_w ? 1024 : 2048;
    const long bid = is_w ? (blockIdx.x - 2048) : blockIdx.x;

    float m = 0.0f;
    long i = bid * blockDim.x + threadIdx.x;
    const long stride = nb * blockDim.x;
    for (; i < n4; i += stride) {
        float4 v = in4[i];
        m = fmaxf(m, fmaxf(fmaxf(fabsf(v.x), fabsf(v.y)), fmaxf(fabsf(v.z), fabsf(v.w))));
    }
    #pragma unroll
    for (int o = 16; o > 0; o >>= 1)
        m = fmaxf(m, __shfl_xor_sync(0xFFFFFFFFu, m, o));
    if ((threadIdx.x & 31) == 0)
        atomicMax(is_w ? &g_amax_w : &g_amax_x, __float_as_uint(m));
}

// ============================================================================
// Pass 2: fused quantize of BOTH tensors — clip(rint(t/scale), ±127)
//   Values are integers in [-127,127]: exactly representable in bf16.
//   blocks [0, 8192) -> x ; blocks [8192, 12288) -> w
// ============================================================================
__global__ void quant_both_kernel(const float* __restrict__ x, const float* __restrict__ w) {
    const bool is_w = blockIdx.x >= 8192;
    const float4* in4 = reinterpret_cast<const float4*>(is_w ? w : x);
    __nv_bfloat162* q2 = reinterpret_cast<__nv_bfloat162*>(is_w ? g_wq : g_xq);
    const long n4 = is_w ? ((long)NN * KK / 4) : ((long)MM * KK / 4);
    const long nb = is_w ? 4096 : 8192;
    const long bid = is_w ? (blockIdx.x - 8192) : blockIdx.x;
    const float amax = __uint_as_float(is_w ? g_amax_w : g_amax_x);
    const float scale = amax / 127.0f;

    long i = bid * blockDim.x + threadIdx.x;
    const long stride = nb * blockDim.x;
    for (; i < n4; i += stride) {
        float4 v = in4[i];
        float a = fminf(fmaxf(rintf(v.x / scale), -127.0f), 127.0f);
        float b = fminf(fmaxf(rintf(v.y / scale), -127.0f), 127.0f);
        float c = fminf(fmaxf(rintf(v.z / scale), -127.0f), 127.0f);
        float d = fminf(fmaxf(rintf(v.w / scale), -127.0f), 127.0f);
        q2[2 * i + 0] = __floats2bfloat162_rn(a, b);
        q2[2 * i + 1] = __floats2bfloat162_rn(c, d);
    }
}

// ============================================================================
// Pass 3: bf16 GEMM  out[M,N] = Xq[M,K] @ Wq[N,K]^T * s + bias
//   BM=128, BN=128, BK=32; 256 threads = 8 warps in 4(M) x 2(N), each warp a
//   32x64 tile (c[2][8][4] = 64 accum regs -> ~115 regs, no spills at 2 CTA/SM)
//   => 2 CTAs/SM x 8 warps = 4 warps/SMSP for HMMA latency hiding.
//   ldmatrix.x4 fragment loads; 4-stage cp.async; 80B-padded rows.
// ============================================================================
static constexpr int BK = 32;                  // bf16 elems per K chunk (64B rows)
static constexpr int NKT = KK / BK;            // 128 k-tiles
static constexpr int ROW_PAD = 80;             // 64B data + 16B pad (conflict-free)
static constexpr int A_STAGE = 128 * ROW_PAD;  // 10240 B
static constexpr int STAGE_BYTES = 2 * A_STAGE;// A + B = 20480 B
static constexpr int NSTAGE = 4;
static constexpr int SMEM_BYTES = NSTAGE * STAGE_BYTES;  // 81920 B (2 CTAs/SM)

__device__ __forceinline__ void stage_copy(uint32_t sbase, int kt, int m0, int n0, int tid) {
    const size_t kofs = (size_t)kt * BK;       // element offset
    #pragma unroll
    for (int i = 0; i < 2; i++) {
        int idx = tid + i * 256;               // 0..511
        int row = idx >> 2, ch = idx & 3;      // 4 x 16B chunks per 64B row
        CP_ASYNC16(sbase + row * ROW_PAD + ch * 16,
                   (const void*)(g_xq + (size_t)(m0 + row) * KK + kofs + ch * 8));
    }
    #pragma unroll
    for (int i = 0; i < 2; i++) {
        int idx = tid + i * 256;
        int row = idx >> 2, ch = idx & 3;
        CP_ASYNC16(sbase + A_STAGE + row * ROW_PAD + ch * 16,
                   (const void*)(g_wq + (size_t)(n0 + row) * KK + kofs + ch * 8));
    }
}

extern "C" __global__ void __launch_bounds__(256, 2)
gemm_kernel(const float* __restrict__ bias, float* __restrict__ out) {
    extern __shared__ char smem[];
    const uint32_t sb = smem_u32(smem);
    const int tid = threadIdx.x;
    const int wid = tid >> 5;
    const int lane = tid & 31;
    const int warp_m = wid & 3;          // 4 warps along M (32 rows each)
    const int warp_n = wid >> 2;         // 2 warps along N (64 cols each)
    const int m0 = blockIdx.y * 128;
    const int n0 = blockIdx.x * 128;

    float c[2][8][4];
    #pragma unroll
    for (int mt = 0; mt < 2; mt++)
        #pragma unroll
        for (int nt = 0; nt < 8; nt++)
            #pragma unroll
            for (int j = 0; j < 4; j++) c[mt][nt][j] = 0.0f;

    // Prologue: fill stages 0..2
    #pragma unroll
    for (int s = 0; s < NSTAGE - 1; s++) {
        stage_copy(sb + s * STAGE_BYTES, s, m0, n0, tid);
        CP_COMMIT();
    }

    // ldmatrix lane addressing: row = lane&15, +16B for lanes 16..31
    const int lrow = lane & 15;
    const int lhalf = (lane >> 4) * 16;

    for (int kt = 0; kt < NKT; kt++) {
        CP_WAIT2();
        __syncthreads();

        if (kt + NSTAGE - 1 < NKT)
            stage_copy(sb + ((kt + NSTAGE - 1) & (NSTAGE - 1)) * STAGE_BYTES,
                       kt + NSTAGE - 1, m0, n0, tid);
        CP_COMMIT();

        const uint32_t sA = sb + (kt & (NSTAGE - 1)) * STAGE_BYTES;
        const uint32_t sB = sA + A_STAGE;

        // Two k16 sub-steps within the 32-elem (64B) K chunk
        #pragma unroll
        for (int kp = 0; kp < 2; kp++) {
            // A frags: r0=(m0-7,k0-7) r1=(m8-15,k0-7) r2=(m0-7,k8-15) r3=(m8-15,k8-15)
            uint32_t a[2][4];
            #pragma unroll
            for (int mt = 0; mt < 2; mt++)
                ldsm_x4(a[mt], sA + (warp_m * 32 + mt * 16 + lrow) * ROW_PAD + kp * 32 + lhalf);
            // B frags: pair of nt per ldmatrix: r0=b0(even) r1=b0(odd) r2=b1(even) r3=b1(odd)
            uint32_t b[8][2];
            #pragma unroll
            for (int np = 0; np < 4; np++) {
                uint32_t r[4];
                ldsm_x4(r, sB + (warp_n * 64 + np * 16 + lrow) * ROW_PAD + kp * 32 + lhalf);
                b[2 * np + 0][0] = r[0]; b[2 * np + 0][1] = r[2];
                b[2 * np + 1][0] = r[1]; b[2 * np + 1][1] = r[3];
            }
            #pragma unroll
            for (int mt = 0; mt < 2; mt++)
                #pragma unroll
                for (int nt = 0; nt < 8; nt++)
                    hmma16816(c[mt][nt], a[mt], b[nt]);
        }
        __syncthreads();
    }
    CP_WAIT0();

    // Epilogue: dequant + bias
    const float sx = __uint_as_float(g_amax_x) / 127.0f;
    const float sw = __uint_as_float(g_amax_w) / 127.0f;
    const float s = sx * sw;

    #pragma unroll
    for (int mt = 0; mt < 2; mt++) {
        #pragma unroll
        for (int half = 0; half < 2; half++) {
            int row = m0 + warp_m * 32 + mt * 16 + (lane >> 2) + half * 8;
            float* orow = out + (size_t)row * NN;
            #pragma unroll
            for (int nt = 0; nt < 8; nt++) {
                int col = n0 + warp_n * 64 + nt * 8 + (lane & 3) * 2;
                float2 o;
                o.x = c[mt][nt][half * 2 + 0] * s + __ldg(&bias[col]);
                o.y = c[mt][nt][half * 2 + 1] * s + __ldg(&bias[col + 1]);
                *reinterpret_cast<float2*>(orow + col) = o;
            }
        }
    }
}

// ============================================================================
// kernel_launch — graph-capturable, allocation-free
// ============================================================================
extern "C" void kernel_launch(void* const* d_in, const int* in_sizes, int n_in,
                              void* d_out, int out_size) {
    const float* x    = (const float*)d_in[0];   // [M, K]
    const float* w    = (const float*)d_in[1];   // [N, K]
    const float* bias = (const float*)d_in[2];   // [N]
    float* out        = (float*)d_out;           // [M, N]

    reset_kernel<<<1, 1>>>();
    absmax_both_kernel<<<3072, 256>>>(x, w);
    quant_both_kernel<<<12288, 256>>>(x, w);

    static bool attr_set = false;
    if (!attr_set) {
        cudaFuncSetAttribute(gemm_kernel, cudaFuncAttributeMaxDynamicSharedMemorySize, SMEM_BYTES);
        attr_set = true;
    }
    gemm_kernel<<<dim3(NN / 128, MM / 128, 1), 256, SMEM_BYTES>>>(bias, out);
}

// round 10
// speedup vs baseline: 2.5641x; 1.0473x over previous
#include <cuda_runtime.h>
#include <cuda_bf16.h>
#include <cstdint>
#include <cstddef>

// ============================================================================
// Problem dims
// ============================================================================
#define MM 8192
#define KK 4096
#define NN 4096

// ============================================================================
// Device scratch (allowed: __device__ globals, no runtime allocation)
// ============================================================================
__device__ unsigned g_amax_x;
__device__ unsigned g_amax_w;
__device__ __nv_bfloat16 g_xq[(size_t)MM * KK];   // quantized activations (exact ints in bf16)
__device__ __nv_bfloat16 g_wq[(size_t)NN * KK];   // quantized weights

// ============================================================================
// PTX helpers — family-generic (sm_80+ PTX only; NO tcgen05 on this target!)
// ============================================================================
__device__ __forceinline__ uint32_t smem_u32(const void* p) {
    uint32_t a;
    asm("{ .reg .u64 t; cvta.to.shared.u64 t, %1; cvt.u32.u64 %0, t; }" : "=r"(a) : "l"(p));
    return a;
}

#define CP_ASYNC16(dst, src) \
    asm volatile("cp.async.cg.shared.global [%0], [%1], 16;" :: "r"(dst), "l"(src) : "memory")
#define CP_COMMIT() asm volatile("cp.async.commit_group;" ::: "memory")
#define CP_WAIT1()  asm volatile("cp.async.wait_group 1;" ::: "memory")
#define CP_WAIT0()  asm volatile("cp.async.wait_group 0;" ::: "memory")

// bf16 warp MMA: D(16x8,f32) = A(16x16,bf16,row) * B(16x8,bf16,col) + D
__device__ __forceinline__ void hmma16816(float* c, const uint32_t* a, const uint32_t* b) {
    asm volatile(
        "mma.sync.aligned.m16n8k16.row.col.f32.bf16.bf16.f32 "
        "{%0,%1,%2,%3}, {%4,%5,%6,%7}, {%8,%9}, {%0,%1,%2,%3};"
        : "+f"(c[0]), "+f"(c[1]), "+f"(c[2]), "+f"(c[3])
        : "r"(a[0]), "r"(a[1]), "r"(a[2]), "r"(a[3]), "r"(b[0]), "r"(b[1]));
}

// ldmatrix x4: four 8x8 b16 matrices; lane l supplies the row address for its group
__device__ __forceinline__ void ldsm_x4(uint32_t* r, uint32_t addr) {
    asm volatile("ldmatrix.sync.aligned.m8n8.x4.shared.b16 {%0,%1,%2,%3}, [%4];"
                 : "=r"(r[0]), "=r"(r[1]), "=r"(r[2]), "=r"(r[3]) : "r"(addr));
}

// ============================================================================
// Pass 0: reset scales
// ============================================================================
__global__ void reset_kernel() {
    g_amax_x = 0u;
    g_amax_w = 0u;
}

// ============================================================================
// Pass 1: fused abs-max over BOTH tensors in one launch
//   blocks [0, 2048) -> x ; blocks [2048, 3072) -> w
// ============================================================================
__global__ void absmax_both_kernel(const float* __restrict__ x, const float* __restrict__ w) {
    const bool is_w = blockIdx.x >= 2048;
    const float4* in4 = reinterpret_cast<const float4*>(is_w ? w : x);
    const long n4 = is_w ? ((long)NN * KK / 4) : ((long)MM * KK / 4);
    const long nb = is_w ? 1024 : 2048;
    const long bid = is_w ? (blockIdx.x - 2048) : blockIdx.x;

    float m = 0.0f;
    long i = bid * blockDim.x + threadIdx.x;
    const long stride = nb * blockDim.x;
    for (; i < n4; i += stride) {
        float4 v = in4[i];
        m = fmaxf(m, fmaxf(fmaxf(fabsf(v.x), fabsf(v.y)), fmaxf(fabsf(v.z), fabsf(v.w))));
    }
    #pragma unroll
    for (int o = 16; o > 0; o >>= 1)
        m = fmaxf(m, __shfl_xor_sync(0xFFFFFFFFu, m, o));
    if ((threadIdx.x & 31) == 0)
        atomicMax(is_w ? &g_amax_w : &g_amax_x, __float_as_uint(m));
}

// ============================================================================
// Pass 2: fused quantize of BOTH tensors — clip(rint(t/scale), ±127)
//   Values are integers in [-127,127]: exactly representable in bf16.
//   blocks [0, 8192) -> x ; blocks [8192, 12288) -> w
// ============================================================================
__global__ void quant_both_kernel(const float* __restrict__ x, const float* __restrict__ w) {
    const bool is_w = blockIdx.x >= 8192;
    const float4* in4 = reinterpret_cast<const float4*>(is_w ? w : x);
    __nv_bfloat162* q2 = reinterpret_cast<__nv_bfloat162*>(is_w ? g_wq : g_xq);
    const long n4 = is_w ? ((long)NN * KK / 4) : ((long)MM * KK / 4);
    const long nb = is_w ? 4096 : 8192;
    const long bid = is_w ? (blockIdx.x - 8192) : blockIdx.x;
    const float amax = __uint_as_float(is_w ? g_amax_w : g_amax_x);
    const float scale = amax / 127.0f;

    long i = bid * blockDim.x + threadIdx.x;
    const long stride = nb * blockDim.x;
    for (; i < n4; i += stride) {
        float4 v = in4[i];
        float a = fminf(fmaxf(rintf(v.x / scale), -127.0f), 127.0f);
        float b = fminf(fmaxf(rintf(v.y / scale), -127.0f), 127.0f);
        float c = fminf(fmaxf(rintf(v.z / scale), -127.0f), 127.0f);
        float d = fminf(fmaxf(rintf(v.w / scale), -127.0f), 127.0f);
        q2[2 * i + 0] = __floats2bfloat162_rn(a, b);
        q2[2 * i + 1] = __floats2bfloat162_rn(c, d);
    }
}

// ============================================================================
// Pass 3: bf16 GEMM  out[M,N] = Xq[M,K] @ Wq[N,K]^T * s + bias
//   BM=128, BN=128, BK=64 (128B rows, 144B padded); 256 threads = 8 warps in
//   4(M) x 2(N), warp tile 32x64 (c[2][8][4]); ldmatrix.x4; 3-stage cp.async;
//   ONE __syncthreads per k-tile; 2 CTAs/SM (regs<=128, no spills).
// ============================================================================
static constexpr int BK = 64;                  // bf16 elems per K chunk (128B rows)
static constexpr int NKT = KK / BK;            // 64 k-tiles
static constexpr int ROW_PAD = 144;            // 128B data + 16B pad (conflict-free)
static constexpr int A_STAGE = 128 * ROW_PAD;  // 18432 B
static constexpr int STAGE_BYTES = 2 * A_STAGE;// A + B = 36864 B
static constexpr int NSTAGE = 3;
static constexpr int SMEM_BYTES = NSTAGE * STAGE_BYTES;  // 110592 B (2 CTAs/SM)

__device__ __forceinline__ void stage_copy(uint32_t sbase, int kt, int m0, int n0, int tid) {
    const size_t kofs = (size_t)kt * BK;       // element offset
    // A: 128 rows x 8 chunks of 16B = 1024 copies; 4 per thread
    #pragma unroll
    for (int i = 0; i < 4; i++) {
        int idx = tid + i * 256;               // 0..1023
        int row = idx >> 3, ch = idx & 7;
        CP_ASYNC16(sbase + row * ROW_PAD + ch * 16,
                   (const void*)(g_xq + (size_t)(m0 + row) * KK + kofs + ch * 8));
    }
    // B: 128 rows x 8 chunks
    #pragma unroll
    for (int i = 0; i < 4; i++) {
        int idx = tid + i * 256;
        int row = idx >> 3, ch = idx & 7;
        CP_ASYNC16(sbase + A_STAGE + row * ROW_PAD + ch * 16,
                   (const void*)(g_wq + (size_t)(n0 + row) * KK + kofs + ch * 8));
    }
}

extern "C" __global__ void __launch_bounds__(256, 2)
gemm_kernel(const float* __restrict__ bias, float* __restrict__ out) {
    extern __shared__ char smem[];
    const uint32_t sb = smem_u32(smem);
    const int tid = threadIdx.x;
    const int wid = tid >> 5;
    const int lane = tid & 31;
    const int warp_m = wid & 3;          // 4 warps along M (32 rows each)
    const int warp_n = wid >> 2;         // 2 warps along N (64 cols each)
    const int m0 = blockIdx.y * 128;
    const int n0 = blockIdx.x * 128;

    float c[2][8][4];
    #pragma unroll
    for (int mt = 0; mt < 2; mt++)
        #pragma unroll
        for (int nt = 0; nt < 8; nt++)
            #pragma unroll
            for (int j = 0; j < 4; j++) c[mt][nt][j] = 0.0f;

    // Prologue: fill stages 0..1
    #pragma unroll
    for (int s = 0; s < NSTAGE - 1; s++) {
        stage_copy(sb + s * STAGE_BYTES, s, m0, n0, tid);
        CP_COMMIT();
    }

    // ldmatrix lane addressing: row = lane&15, +16B for lanes 16..31
    const int lrow = lane & 15;
    const int lhalf = (lane >> 4) * 16;

    for (int kt = 0; kt < NKT; kt++) {
        CP_WAIT1();            // stage kt resident
        __syncthreads();       // visibility + write-safety for the copy below

        // Copy stage kt+2 -> buffer (kt+2)%3 == (kt-1)%3, whose compute
        // finished before the barrier above. Always commit to keep counts.
        if (kt + NSTAGE - 1 < NKT)
            stage_copy(sb + ((kt + NSTAGE - 1) % NSTAGE) * STAGE_BYTES,
                       kt + NSTAGE - 1, m0, n0, tid);
        CP_COMMIT();

        const uint32_t sA = sb + (kt % NSTAGE) * STAGE_BYTES;
        const uint32_t sB = sA + A_STAGE;

        // Four k16 sub-steps within the 64-elem (128B) K chunk
        #pragma unroll
        for (int kp = 0; kp < 4; kp++) {
            uint32_t a[2][4];
            #pragma unroll
            for (int mt = 0; mt < 2; mt++)
                ldsm_x4(a[mt], sA + (warp_m * 32 + mt * 16 + lrow) * ROW_PAD + kp * 32 + lhalf);
            uint32_t b[8][2];
            #pragma unroll
            for (int np = 0; np < 4; np++) {
                uint32_t r[4];
                ldsm_x4(r, sB + (warp_n * 64 + np * 16 + lrow) * ROW_PAD + kp * 32 + lhalf);
                b[2 * np + 0][0] = r[0]; b[2 * np + 0][1] = r[2];
                b[2 * np + 1][0] = r[1]; b[2 * np + 1][1] = r[3];
            }
            #pragma unroll
            for (int mt = 0; mt < 2; mt++)
                #pragma unroll
                for (int nt = 0; nt < 8; nt++)
                    hmma16816(c[mt][nt], a[mt], b[nt]);
        }
    }
    CP_WAIT0();

    // Epilogue: dequant + bias
    const float sx = __uint_as_float(g_amax_x) / 127.0f;
    const float sw = __uint_as_float(g_amax_w) / 127.0f;
    const float s = sx * sw;

    #pragma unroll
    for (int mt = 0; mt < 2; mt++) {
        #pragma unroll
        for (int half = 0; half < 2; half++) {
            int row = m0 + warp_m * 32 + mt * 16 + (lane >> 2) + half * 8;
            float* orow = out + (size_t)row * NN;
            #pragma unroll
            for (int nt = 0; nt < 8; nt++) {
                int col = n0 + warp_n * 64 + nt * 8 + (lane & 3) * 2;
                float2 o;
                o.x = c[mt][nt][half * 2 + 0] * s + __ldg(&bias[col]);
                o.y = c[mt][nt][half * 2 + 1] * s + __ldg(&bias[col + 1]);
                *reinterpret_cast<float2*>(orow + col) = o;
            }
        }
    }
}

// ============================================================================
// kernel_launch — graph-capturable, allocation-free
// ============================================================================
extern "C" void kernel_launch(void* const* d_in, const int* in_sizes, int n_in,
                              void* d_out, int out_size) {
    const float* x    = (const float*)d_in[0];   // [M, K]
    const float* w    = (const float*)d_in[1];   // [N, K]
    const float* bias = (const float*)d_in[2];   // [N]
    float* out        = (float*)d_out;           // [M, N]

    reset_kernel<<<1, 1>>>();
    absmax_both_kernel<<<3072, 256>>>(x, w);
    quant_both_kernel<<<12288, 256>>>(x, w);

    static bool attr_set = false;
    if (!attr_set) {
        cudaFuncSetAttribute(gemm_kernel, cudaFuncAttributeMaxDynamicSharedMemorySize, SMEM_BYTES);
        attr_set = true;
    }
    gemm_kernel<<<dim3(NN / 128, MM / 128, 1), 256, SMEM_BYTES>>>(bias, out);
}